// round 1
// baseline (speedup 1.0000x reference)
#include <cuda_runtime.h>
#include <cuda_bf16.h>

#define N_NODES 50000
#define H_DIM   128
#define F_DIM   256
#define C_DIM   40

// Scratch buffers (static device globals — no allocation allowed)
__device__ float g_X[N_NODES * H_DIM];   // layer input / activation
__device__ float g_H[N_NODES * H_DIM];   // x @ W (pre-aggregation), row-scaled
__device__ float g_M[N_NODES * H_DIM];   // aggregation accumulator
__device__ float g_degout[N_NODES];      // becomes rsqrt(max(deg_out,1))
__device__ float g_degin[N_NODES];       // becomes rsqrt(max(deg_in,1))

// ---------------------------------------------------------------------------
// small elementwise kernels
// ---------------------------------------------------------------------------
__global__ void zero_deg_kernel() {
    int i = blockIdx.x * blockDim.x + threadIdx.x;
    if (i < N_NODES) { g_degout[i] = 0.f; g_degin[i] = 0.f; }
}

__global__ void zero_m_kernel() {
    int i = blockIdx.x * blockDim.x + threadIdx.x;
    if (i < (N_NODES * H_DIM) / 4) {
        reinterpret_cast<float4*>(g_M)[i] = make_float4(0.f, 0.f, 0.f, 0.f);
    }
}

__global__ void deg_kernel(const int* __restrict__ src, const int* __restrict__ dst, int E) {
    int i = blockIdx.x * blockDim.x + threadIdx.x;
    if (i < E) {
        atomicAdd(&g_degout[src[i]], 1.f);
        atomicAdd(&g_degin[dst[i]], 1.f);
    }
}

__global__ void rsqrt_kernel() {
    int i = blockIdx.x * blockDim.x + threadIdx.x;
    if (i < N_NODES) {
        g_degout[i] = rsqrtf(fmaxf(g_degout[i], 1.f));
        g_degin[i]  = rsqrtf(fmaxf(g_degin[i], 1.f));
    }
}

// x = relu(m * rinv_in[row] + bias[col])
__global__ void finalize_kernel(const float* __restrict__ bias) {
    int i = blockIdx.x * blockDim.x + threadIdx.x;
    if (i < N_NODES * H_DIM) {
        int row = i >> 7;        // / 128
        int col = i & 127;
        float v = g_M[i] * g_degin[row] + bias[col];
        g_X[i] = fmaxf(v, 0.f);
    }
}

// ---------------------------------------------------------------------------
// edge aggregation: one warp per edge, one float4 per lane (128 floats/row)
// m[dst] += h[src]  via vector red.global.add
// ---------------------------------------------------------------------------
__global__ void aggregate_kernel(const int* __restrict__ src, const int* __restrict__ dst, int E) {
    int warp = (blockIdx.x * blockDim.x + threadIdx.x) >> 5;
    int lane = threadIdx.x & 31;
    if (warp >= E) return;
    int s = src[warp];
    int d = dst[warp];
    float4 v = reinterpret_cast<const float4*>(g_H)[s * 32 + lane];
    float* md = g_M + (size_t)d * H_DIM + lane * 4;
    asm volatile("red.global.add.v4.f32 [%0], {%1,%2,%3,%4};"
                 :: "l"(md), "f"(v.x), "f"(v.y), "f"(v.z), "f"(v.w)
                 : "memory");
}

// ---------------------------------------------------------------------------
// fp32 SGEMM: C[M,N] = A[M,K] @ B[K,N], epilogue: *rowscale, +bias, relu
// BM=BN=64, BK=16, 256 threads, 4x4 per thread. K must be a multiple of 16.
// ---------------------------------------------------------------------------
__global__ __launch_bounds__(256) void sgemm_kernel(
    const float* __restrict__ A, const float* __restrict__ B, float* __restrict__ C,
    int M, int N, int K,
    const float* __restrict__ bias, const float* __restrict__ rowscale, int do_relu)
{
    const int BM = 64, BN = 64, BK = 16;
    __shared__ float As[BK][BM + 4];
    __shared__ float Bs[BK][BN + 4];

    int tid = threadIdx.x;
    int tx = tid & 15;      // 0..15 -> 4 cols each
    int ty = tid >> 4;      // 0..15 -> 4 rows each
    int rowBase = blockIdx.y * BM;
    int colBase = blockIdx.x * BN;

    float acc[4][4] = {};

    for (int k0 = 0; k0 < K; k0 += BK) {
        // load A tile (BM x BK), transposed into As[k][m]
        #pragma unroll
        for (int i = 0; i < 4; i++) {
            int e = tid + i * 256;
            int r = e >> 4;          // / BK
            int c = e & 15;          // % BK
            int gr = rowBase + r;
            As[c][r] = (gr < M) ? A[(size_t)gr * K + k0 + c] : 0.f;
        }
        // load B tile (BK x BN)
        #pragma unroll
        for (int i = 0; i < 4; i++) {
            int e = tid + i * 256;
            int r = e >> 6;          // / BN
            int c = e & 63;          // % BN
            int gc = colBase + c;
            Bs[r][c] = (gc < N) ? B[(size_t)(k0 + r) * N + gc] : 0.f;
        }
        __syncthreads();

        #pragma unroll
        for (int k = 0; k < BK; k++) {
            float a[4], b[4];
            #pragma unroll
            for (int i = 0; i < 4; i++) a[i] = As[k][ty * 4 + i];
            #pragma unroll
            for (int j = 0; j < 4; j++) b[j] = Bs[k][tx * 4 + j];
            #pragma unroll
            for (int i = 0; i < 4; i++)
                #pragma unroll
                for (int j = 0; j < 4; j++)
                    acc[i][j] = fmaf(a[i], b[j], acc[i][j]);
        }
        __syncthreads();
    }

    #pragma unroll
    for (int i = 0; i < 4; i++) {
        int r = rowBase + ty * 4 + i;
        if (r >= M) continue;
        float rs = rowscale ? rowscale[r] : 1.f;
        #pragma unroll
        for (int j = 0; j < 4; j++) {
            int c = colBase + tx * 4 + j;
            if (c >= N) continue;
            float v = acc[i][j] * rs;
            if (bias) v += bias[c];
            if (do_relu) v = fmaxf(v, 0.f);
            C[(size_t)r * N + c] = v;
        }
    }
}

// ---------------------------------------------------------------------------
extern "C" void kernel_launch(void* const* d_in, const int* in_sizes, int n_in,
                              void* d_out, int out_size)
{
    const float* n_feats = (const float*)d_in[0];
    const int*   src     = (const int*)  d_in[1];
    const int*   dst     = (const int*)  d_in[2];
    const float* Wp      = (const float*)d_in[3];
    const float* bp      = (const float*)d_in[4];
    const float* W1      = (const float*)d_in[5];
    const float* b1      = (const float*)d_in[6];
    const float* W2      = (const float*)d_in[7];
    const float* b2      = (const float*)d_in[8];
    const float* Wc      = (const float*)d_in[9];
    const float* bc      = (const float*)d_in[10];
    float* out = (float*)d_out;
    int E = in_sizes[1];

    float *X, *H, *degout;
    cudaGetSymbolAddress((void**)&X, g_X);
    cudaGetSymbolAddress((void**)&H, g_H);
    cudaGetSymbolAddress((void**)&degout, g_degout);

    const int T = 256;
    int nodeBlocks = (N_NODES + T - 1) / T;
    int edgeBlocks = (E + T - 1) / T;
    int aggBlocks  = (E + 7) / 8;                 // 8 warps per block, 1 warp/edge
    int elemBlocks = (N_NODES * H_DIM + T - 1) / T;
    int zeroBlocks = (N_NODES * H_DIM / 4 + T - 1) / T;

    dim3 gH((H_DIM + 63) / 64, (N_NODES + 63) / 64);   // (2, 782)
    dim3 gC((C_DIM + 63) / 64, (N_NODES + 63) / 64);   // (1, 782)

    // degrees -> rsqrt
    zero_deg_kernel<<<nodeBlocks, T>>>();
    deg_kernel<<<edgeBlocks, T>>>(src, dst, E);
    rsqrt_kernel<<<nodeBlocks, T>>>();

    // projection: X = n_feats @ Wp + bp
    sgemm_kernel<<<gH, T>>>(n_feats, Wp, X, N_NODES, H_DIM, F_DIM, bp, nullptr, 0);

    // ---- GCN layer 1 ----
    sgemm_kernel<<<gH, T>>>(X, W1, H, N_NODES, H_DIM, H_DIM, nullptr, degout, 0);
    zero_m_kernel<<<zeroBlocks, T>>>();
    aggregate_kernel<<<aggBlocks, T>>>(src, dst, E);
    finalize_kernel<<<elemBlocks, T>>>(b1);

    // ---- GCN layer 2 ----
    sgemm_kernel<<<gH, T>>>(X, W2, H, N_NODES, H_DIM, H_DIM, nullptr, degout, 0);
    zero_m_kernel<<<zeroBlocks, T>>>();
    aggregate_kernel<<<aggBlocks, T>>>(src, dst, E);
    finalize_kernel<<<elemBlocks, T>>>(b2);

    // classifier: out = X @ Wc + bc
    sgemm_kernel<<<gC, T>>>(X, Wc, out, N_NODES, C_DIM, H_DIM, bc, nullptr, 0);
}

// round 2
// speedup vs baseline: 1.2564x; 1.2564x over previous
#include <cuda_runtime.h>
#include <cuda_bf16.h>
#include <cstdint>

#define N_NODES 50000
#define H_DIM   128
#define F_DIM   256
#define C_DIM   40

// Scratch buffers (static device globals — no allocation allowed)
__device__ float g_X[N_NODES * H_DIM];   // layer input / activation
__device__ float g_H[N_NODES * H_DIM];   // x @ W (pre-aggregation), row-scaled
__device__ float g_M[N_NODES * H_DIM];   // aggregation accumulator
__device__ float g_degout[N_NODES];      // becomes rsqrt(max(deg_out,1))
__device__ float g_degin[N_NODES];       // becomes rsqrt(max(deg_in,1))

// ---------------------------------------------------------------------------
// small elementwise kernels
// ---------------------------------------------------------------------------
__global__ void zero_deg_kernel() {
    int i = blockIdx.x * blockDim.x + threadIdx.x;
    if (i < N_NODES) { g_degout[i] = 0.f; g_degin[i] = 0.f; }
}

__global__ void zero_m_kernel() {
    int i = blockIdx.x * blockDim.x + threadIdx.x;
    if (i < (N_NODES * H_DIM) / 4) {
        reinterpret_cast<float4*>(g_M)[i] = make_float4(0.f, 0.f, 0.f, 0.f);
    }
}

__global__ void deg_kernel(const int* __restrict__ src, const int* __restrict__ dst, int E) {
    int i = blockIdx.x * blockDim.x + threadIdx.x;
    if (i < E) {
        atomicAdd(&g_degout[src[i]], 1.f);
        atomicAdd(&g_degin[dst[i]], 1.f);
    }
}

__global__ void rsqrt_kernel() {
    int i = blockIdx.x * blockDim.x + threadIdx.x;
    if (i < N_NODES) {
        g_degout[i] = rsqrtf(fmaxf(g_degout[i], 1.f));
        g_degin[i]  = rsqrtf(fmaxf(g_degin[i], 1.f));
    }
}

// x = relu(m * rinv_in[row] + bias[col])
__global__ void finalize_kernel(const float* __restrict__ bias) {
    int i = blockIdx.x * blockDim.x + threadIdx.x;
    if (i < N_NODES * H_DIM) {
        int row = i >> 7;        // / 128
        int col = i & 127;
        float v = g_M[i] * g_degin[row] + bias[col];
        g_X[i] = fmaxf(v, 0.f);
    }
}

// ---------------------------------------------------------------------------
// edge aggregation: one warp per edge, one float4 per lane (128 floats/row)
// m[dst] += h[src]  via vector red.global.add
// ---------------------------------------------------------------------------
__global__ void aggregate_kernel(const int* __restrict__ src, const int* __restrict__ dst, int E) {
    int warp = (blockIdx.x * blockDim.x + threadIdx.x) >> 5;
    int lane = threadIdx.x & 31;
    if (warp >= E) return;
    int s = src[warp];
    int d = dst[warp];
    float4 v = reinterpret_cast<const float4*>(g_H)[s * 32 + lane];
    float* md = g_M + (size_t)d * H_DIM + lane * 4;
    asm volatile("red.global.add.v4.f32 [%0], {%1,%2,%3,%4};"
                 :: "l"(md), "f"(v.x), "f"(v.y), "f"(v.z), "f"(v.w)
                 : "memory");
}

// ---------------------------------------------------------------------------
// 3xTF32 tensor-core GEMM: C[M,N] = A[M,K] @ B[K,N]
// epilogue: *rowscale[row], +bias[col], optional relu
// BM=128, BN=64, BK=32, 256 threads (8 warps: 4m x 2n), warp tile 32x32.
// Requires K % 32 == 0. Handles ragged M and N (guards).
// ---------------------------------------------------------------------------
#define GBM 128
#define GBN 64
#define GBK 32
#define A_STRIDE (GBK + 4)   // 36 floats -> conflict-free frag loads (4r+q)
#define B_STRIDE (GBN + 8)   // 72 floats -> conflict-free frag loads (8q+r)

__device__ __forceinline__ void split_tf32(float x, uint32_t& hi, uint32_t& lo) {
    uint32_t h;
    asm("cvt.rna.tf32.f32 %0, %1;" : "=r"(h) : "f"(x));
    float r = x - __uint_as_float(h);
    asm("cvt.rna.tf32.f32 %0, %1;" : "=r"(lo) : "f"(r));
    hi = h;
}

__device__ __forceinline__ void mma_tf32(
    float& d0, float& d1, float& d2, float& d3,
    uint32_t a0, uint32_t a1, uint32_t a2, uint32_t a3,
    uint32_t b0, uint32_t b1)
{
    asm volatile(
        "mma.sync.aligned.m16n8k8.row.col.f32.tf32.tf32.f32 "
        "{%0,%1,%2,%3}, {%4,%5,%6,%7}, {%8,%9}, {%0,%1,%2,%3};"
        : "+f"(d0), "+f"(d1), "+f"(d2), "+f"(d3)
        : "r"(a0), "r"(a1), "r"(a2), "r"(a3), "r"(b0), "r"(b1));
}

__global__ __launch_bounds__(256) void mma_gemm_kernel(
    const float* __restrict__ A, const float* __restrict__ B, float* __restrict__ C,
    int M, int N, int K,
    const float* __restrict__ bias, const float* __restrict__ rowscale, int do_relu)
{
    __shared__ float As[GBM * A_STRIDE];
    __shared__ float Bs[GBK * B_STRIDE];

    const int tid  = threadIdx.x;
    const int lane = tid & 31;
    const int warp = tid >> 5;
    const int wm   = warp >> 1;   // 0..3 (m direction, 32 rows each)
    const int wn   = warp & 1;    // 0..1 (n direction, 32 cols each)
    const int rowBase = blockIdx.y * GBM;
    const int colBase = blockIdx.x * GBN;

    float acc[2][4][4];
    #pragma unroll
    for (int i = 0; i < 2; i++)
        #pragma unroll
        for (int j = 0; j < 4; j++)
            #pragma unroll
            for (int l = 0; l < 4; l++) acc[i][j][l] = 0.f;

    // --- global load slots ---
    // A tile: 128 rows x 8 float4 = 1024 slots, 4 per thread
    int aRow[4], aC4[4];
    #pragma unroll
    for (int i = 0; i < 4; i++) {
        int idx = tid + i * 256;
        aRow[i] = idx >> 3;
        aC4[i]  = idx & 7;
    }
    // B tile: 32 rows x 16 float4 = 512 slots, 2 per thread
    int bRow[2], bC4[2];
    #pragma unroll
    for (int i = 0; i < 2; i++) {
        int idx = tid + i * 256;
        bRow[i] = idx >> 4;
        bC4[i]  = idx & 15;
    }

    const int nStages = K / GBK;
    float4 pa[4], pb[2];

    // prefetch stage 0
    {
        const int k0 = 0;
        #pragma unroll
        for (int i = 0; i < 4; i++) {
            int gr = rowBase + aRow[i];
            pa[i] = (gr < M) ? *reinterpret_cast<const float4*>(A + (size_t)gr * K + k0 + aC4[i] * 4)
                             : make_float4(0.f, 0.f, 0.f, 0.f);
        }
        #pragma unroll
        for (int i = 0; i < 2; i++) {
            int gc = colBase + bC4[i] * 4;
            pb[i] = (gc < N) ? *reinterpret_cast<const float4*>(B + (size_t)(k0 + bRow[i]) * N + gc)
                             : make_float4(0.f, 0.f, 0.f, 0.f);
        }
    }

    for (int s = 0; s < nStages; s++) {
        // store prefetched tile to smem
        #pragma unroll
        for (int i = 0; i < 4; i++)
            *reinterpret_cast<float4*>(&As[aRow[i] * A_STRIDE + aC4[i] * 4]) = pa[i];
        #pragma unroll
        for (int i = 0; i < 2; i++)
            *reinterpret_cast<float4*>(&Bs[bRow[i] * B_STRIDE + bC4[i] * 4]) = pb[i];
        __syncthreads();

        // prefetch next stage (loads in flight during compute)
        if (s + 1 < nStages) {
            const int k0 = (s + 1) * GBK;
            #pragma unroll
            for (int i = 0; i < 4; i++) {
                int gr = rowBase + aRow[i];
                pa[i] = (gr < M) ? *reinterpret_cast<const float4*>(A + (size_t)gr * K + k0 + aC4[i] * 4)
                                 : make_float4(0.f, 0.f, 0.f, 0.f);
            }
            #pragma unroll
            for (int i = 0; i < 2; i++) {
                int gc = colBase + bC4[i] * 4;
                pb[i] = (gc < N) ? *reinterpret_cast<const float4*>(B + (size_t)(k0 + bRow[i]) * N + gc)
                                 : make_float4(0.f, 0.f, 0.f, 0.f);
            }
        }

        // compute: 4 k8-steps
        #pragma unroll
        for (int kk = 0; kk < 4; kk++) {
            const int kc = kk * 8;
            uint32_t ahi[2][4], alo[2][4];
            #pragma unroll
            for (int mt = 0; mt < 2; mt++) {
                int r = wm * 32 + mt * 16 + (lane >> 2);
                int c = kc + (lane & 3);
                float a0 = As[r * A_STRIDE + c];
                float a1 = As[(r + 8) * A_STRIDE + c];
                float a2 = As[r * A_STRIDE + c + 4];
                float a3 = As[(r + 8) * A_STRIDE + c + 4];
                split_tf32(a0, ahi[mt][0], alo[mt][0]);
                split_tf32(a1, ahi[mt][1], alo[mt][1]);
                split_tf32(a2, ahi[mt][2], alo[mt][2]);
                split_tf32(a3, ahi[mt][3], alo[mt][3]);
            }
            uint32_t bhi[4][2], blo[4][2];
            #pragma unroll
            for (int nt = 0; nt < 4; nt++) {
                int c = wn * 32 + nt * 8 + (lane >> 2);
                int r = kc + (lane & 3);
                float b0 = Bs[r * B_STRIDE + c];
                float b1 = Bs[(r + 4) * B_STRIDE + c];
                split_tf32(b0, bhi[nt][0], blo[nt][0]);
                split_tf32(b1, bhi[nt][1], blo[nt][1]);
            }
            #pragma unroll
            for (int mt = 0; mt < 2; mt++) {
                #pragma unroll
                for (int nt = 0; nt < 4; nt++) {
                    float* d = acc[mt][nt];
                    // hi*hi + lo*hi + hi*lo  (3xTF32)
                    mma_tf32(d[0], d[1], d[2], d[3],
                             ahi[mt][0], ahi[mt][1], ahi[mt][2], ahi[mt][3],
                             bhi[nt][0], bhi[nt][1]);
                    mma_tf32(d[0], d[1], d[2], d[3],
                             alo[mt][0], alo[mt][1], alo[mt][2], alo[mt][3],
                             bhi[nt][0], bhi[nt][1]);
                    mma_tf32(d[0], d[1], d[2], d[3],
                             ahi[mt][0], ahi[mt][1], ahi[mt][2], ahi[mt][3],
                             blo[nt][0], blo[nt][1]);
                }
            }
        }
        __syncthreads();
    }

    // epilogue
    #pragma unroll
    for (int mt = 0; mt < 2; mt++) {
        int r0 = rowBase + wm * 32 + mt * 16 + (lane >> 2);
        int r1 = r0 + 8;
        float rs0 = (rowscale && r0 < M) ? rowscale[r0] : 1.f;
        float rs1 = (rowscale && r1 < M) ? rowscale[r1] : 1.f;
        #pragma unroll
        for (int nt = 0; nt < 4; nt++) {
            int c0 = colBase + wn * 32 + nt * 8 + (lane & 3) * 2;
            #pragma unroll
            for (int half = 0; half < 2; half++) {
                int c = c0 + half;
                if (c >= N) continue;
                float bv = bias ? bias[c] : 0.f;
                if (r0 < M) {
                    float v = acc[mt][nt][half] * rs0 + bv;
                    if (do_relu) v = fmaxf(v, 0.f);
                    C[(size_t)r0 * N + c] = v;
                }
                if (r1 < M) {
                    float v = acc[mt][nt][2 + half] * rs1 + bv;
                    if (do_relu) v = fmaxf(v, 0.f);
                    C[(size_t)r1 * N + c] = v;
                }
            }
        }
    }
}

// ---------------------------------------------------------------------------
extern "C" void kernel_launch(void* const* d_in, const int* in_sizes, int n_in,
                              void* d_out, int out_size)
{
    const float* n_feats = (const float*)d_in[0];
    const int*   src     = (const int*)  d_in[1];
    const int*   dst     = (const int*)  d_in[2];
    const float* Wp      = (const float*)d_in[3];
    const float* bp      = (const float*)d_in[4];
    const float* W1      = (const float*)d_in[5];
    const float* b1      = (const float*)d_in[6];
    const float* W2      = (const float*)d_in[7];
    const float* b2      = (const float*)d_in[8];
    const float* Wc      = (const float*)d_in[9];
    const float* bc      = (const float*)d_in[10];
    float* out = (float*)d_out;
    int E = in_sizes[1];

    float *X, *H, *degout;
    cudaGetSymbolAddress((void**)&X, g_X);
    cudaGetSymbolAddress((void**)&H, g_H);
    cudaGetSymbolAddress((void**)&degout, g_degout);

    const int T = 256;
    int nodeBlocks = (N_NODES + T - 1) / T;
    int edgeBlocks = (E + T - 1) / T;
    int aggBlocks  = (E + 7) / 8;                 // 8 warps per block, 1 warp/edge
    int elemBlocks = (N_NODES * H_DIM + T - 1) / T;
    int zeroBlocks = (N_NODES * H_DIM / 4 + T - 1) / T;

    dim3 gH((H_DIM + GBN - 1) / GBN, (N_NODES + GBM - 1) / GBM);   // (2, 391)
    dim3 gC((C_DIM + GBN - 1) / GBN, (N_NODES + GBM - 1) / GBM);   // (1, 391)

    // degrees -> rsqrt
    zero_deg_kernel<<<nodeBlocks, T>>>();
    deg_kernel<<<edgeBlocks, T>>>(src, dst, E);
    rsqrt_kernel<<<nodeBlocks, T>>>();

    // projection: X = n_feats @ Wp + bp
    mma_gemm_kernel<<<gH, T>>>(n_feats, Wp, X, N_NODES, H_DIM, F_DIM, bp, nullptr, 0);

    // ---- GCN layer 1 ----
    mma_gemm_kernel<<<gH, T>>>(X, W1, H, N_NODES, H_DIM, H_DIM, nullptr, degout, 0);
    zero_m_kernel<<<zeroBlocks, T>>>();
    aggregate_kernel<<<aggBlocks, T>>>(src, dst, E);
    finalize_kernel<<<elemBlocks, T>>>(b1);

    // ---- GCN layer 2 ----
    mma_gemm_kernel<<<gH, T>>>(X, W2, H, N_NODES, H_DIM, H_DIM, nullptr, degout, 0);
    zero_m_kernel<<<zeroBlocks, T>>>();
    aggregate_kernel<<<aggBlocks, T>>>(src, dst, E);
    finalize_kernel<<<elemBlocks, T>>>(b2);

    // classifier: out = X @ Wc + bc
    mma_gemm_kernel<<<gC, T>>>(X, Wc, out, N_NODES, C_DIM, H_DIM, bc, nullptr, 0);
}